// round 12
// baseline (speedup 1.0000x reference)
#include <cuda_runtime.h>
#include <cuda_fp16.h>
#include <cstdint>

#define NSEQ 16384

__device__ __half g_Wh[4096 * 64];        // [ki][j] fp16 W
__device__ float  g_bias[4096];           // [ki]
__device__ __half g_xh[4 * 64 * NSEQ];    // fp16 copy of x, same layout

// smem byte offsets
#define SM_W     0                    // [128 n][64 j] fp16 swizzled (16384)
#define SM_BIAS  16384                // 128 f32                      (512)
#define SM_X     16896                // 4 bufs x [8 warps x 2KB] private A slices
#define SM_XBUF  16384                // one buffer = 8 warps * 2KB
#define SM_TOTAL (16896 + 4 * 16384)  // 82432

__device__ __forceinline__ uint32_t smem_u32(const void *p) {
    uint32_t a;
    asm("{ .reg .u64 t; cvta.to.shared.u64 t, %1; cvt.u32.u64 %0, t; }" : "=r"(a) : "l"(p));
    return a;
}
__device__ __forceinline__ uint32_t h2u(__half2 h) {
    return *reinterpret_cast<const uint32_t *>(&h);
}
__device__ __forceinline__ void ldsm4(uint32_t *r, uint32_t a) {
    asm volatile("ldmatrix.sync.aligned.m8n8.x4.shared.b16 {%0,%1,%2,%3}, [%4];"
                 : "=r"(r[0]), "=r"(r[1]), "=r"(r[2]), "=r"(r[3]) : "r"(a));
}
__device__ __forceinline__ void ldsm4t(uint32_t *r, uint32_t a) {
    asm volatile("ldmatrix.sync.aligned.m8n8.x4.trans.shared.b16 {%0,%1,%2,%3}, [%4];"
                 : "=r"(r[0]), "=r"(r[1]), "=r"(r[2]), "=r"(r[3]) : "r"(a));
}
__device__ __forceinline__ void mma16816(float *c, const uint32_t *a, uint32_t b0, uint32_t b1) {
    asm volatile("mma.sync.aligned.m16n8k16.row.col.f32.f16.f16.f32 "
                 "{%0,%1,%2,%3}, {%4,%5,%6,%7}, {%8,%9}, {%0,%1,%2,%3};"
                 : "+f"(c[0]), "+f"(c[1]), "+f"(c[2]), "+f"(c[3])
                 : "r"(a[0]), "r"(a[1]), "r"(a[2]), "r"(a[3]), "r"(b0), "r"(b1));
}
__device__ __forceinline__ void cpa16(uint32_t dst, const void *src) {
    asm volatile("cp.async.cg.shared.global [%0], [%1], 16;" :: "r"(dst), "l"(src));
}
__device__ __forceinline__ void cpa_commit() {
    asm volatile("cp.async.commit_group;" ::: "memory");
}
template <int N> __device__ __forceinline__ void cpa_wait() {
    asm volatile("cp.async.wait_group %0;" :: "n"(N) : "memory");
}

// ---------------------------------------------------------------------------
// Combined prep (one launch):
//   blocks [0, 1024):    x f32 -> fp16 g_xh (16 elems/thread)
//   blocks [1024, 1280): W -> fp16 g_Wh [ki][j] + bias[ki] = cm[k] . Wcm[k][i]
// ---------------------------------------------------------------------------
__global__ void prep_all(const float *__restrict__ x, const float *__restrict__ W,
                         const float *__restrict__ cm) {
    const int tid = threadIdx.x;
    if (blockIdx.x < 1024) {
        const int t = blockIdx.x * 256 + tid;
        const float4 *src = reinterpret_cast<const float4 *>(x) + (size_t)t * 4;
        uint4 *dst = reinterpret_cast<uint4 *>(g_xh) + (size_t)t * 2;
#pragma unroll
        for (int h = 0; h < 2; ++h) {
            float4 a = src[2 * h], b = src[2 * h + 1];
            uint32_t p0 = h2u(__float22half2_rn(make_float2(a.x, a.y)));
            uint32_t p1 = h2u(__float22half2_rn(make_float2(a.z, a.w)));
            uint32_t p2 = h2u(__float22half2_rn(make_float2(b.x, b.y)));
            uint32_t p3 = h2u(__float22half2_rn(make_float2(b.z, b.w)));
            dst[h] = make_uint4(p0, p1, p2, p3);
        }
    } else {
        const int pb = blockIdx.x - 1024;     // 0..255
#pragma unroll
        for (int t = 0; t < 4; ++t) {
            const int e = pb * 1024 + t * 256 + tid;   // (k, i, j) packed
            const int k = e >> 12, i = (e >> 6) & 63, j = e & 63;
            g_Wh[e] = __float2half_rn(W[(k * 64 + i) * 128 + j]);
        }
        if (tid < 16) {
            const int idx = pb * 16 + tid;    // ki
            const int k = idx >> 6, i = idx & 63;
            const float *cmk = cm + k * 64;
            const float *wc = W + (k * 64 + i) * 128 + 64;
            float s = 0.f;
#pragma unroll 8
            for (int j = 0; j < 64; ++j)
                s = fmaf(cmk[j], wc[j], s);
            g_bias[idx] = s;
        }
    }
}

// ---------------------------------------------------------------------------
// Main: 256 threads (8 warps = 4m x 2n), CTA tile 64m x 128ki, K=64.
// 16 m-tiles per CTA. Each warp stages ITS OWN 2KB A slice (m cols
// [wm*16, wm*16+16)) into a private smem region, layout [2 chunk][64 j][16B]
// -> ldsm reads 256B contiguous, conflict-free, no swizzle. ZERO intra-loop
// __syncthreads: only per-warp cp.async wait ladder. B hoisted. 2 CTAs/SM.
// ---------------------------------------------------------------------------
__global__ __launch_bounds__(256, 2)
void mma_kernel(float *__restrict__ out) {
    extern __shared__ char smem[];
    const uint32_t sb = smem_u32(smem);
    const int tid = threadIdx.x;
    const int lane = tid & 31, wid = tid >> 5;
    const int wm = wid & 3, wn = wid >> 2;
    const int ki0 = blockIdx.x * 128;
    const int grp = blockIdx.y;          // 0..63, 16 m-tiles of 64 each

    // ---- per-warp private staging: 4 cpa16/thread, region [c][j][16B] ----
    // thread element e = lane + 32q: c = e>>6, j = e&63
    const uint32_t wreg = sb + SM_X + (uint32_t)wid * 2048;
    auto stage_x = [&](int t, int buf) {
        const int m0 = (grp * 16 + t) * 64;
        const __half *xb = g_xh + ((size_t)(m0 >> 14) * 64) * NSEQ + (m0 & (NSEQ - 1)) +
                           wm * 16;
        const uint32_t dbase = wreg + (uint32_t)buf * SM_XBUF;
#pragma unroll
        for (int q = 0; q < 4; ++q) {
            const int e = lane + 32 * q;
            const int c = e >> 6, j = e & 63;
            cpa16(dbase + (uint32_t)(c * 1024 + j * 16), xb + (size_t)j * NSEQ + c * 8);
        }
        cpa_commit();
    };

    // prologue: start tiles 0,1,2 in bufs 0,1,2
    stage_x(0, 0);
    stage_x(1, 1);
    stage_x(2, 2);

    // ---- stage W (swizzled, once) + bias ----
    {
#pragma unroll
        for (int q = 0; q < 4; ++q) {
            const int c = tid + q * 256;
            const int n = c >> 3, ch = c & 7;
            const uint4 w = *reinterpret_cast<const uint4 *>(g_Wh + (ki0 + n) * 64 + ch * 8);
            *reinterpret_cast<uint4 *>(smem + SM_W + n * 128 + ((ch ^ (n & 7)) * 16)) = w;
        }
        if (tid < 128) reinterpret_cast<float *>(smem + SM_BIAS)[tid] = g_bias[ki0 + tid];
    }
    __syncthreads();     // the ONLY CTA barrier: W/bias visible to all warps

    // ---- hoist B (W tile) fragments: constant for whole CTA ----
    const int l7 = lane & 7;
    const int rBl = (lane & 7) + ((lane >> 4) << 3);
    const uint32_t aB0 = sb + SM_W + (uint32_t)(wn * 64 + rBl) * 128;
    const int selB = (lane >> 3) & 1;
    uint32_t B[4][4][4];
#pragma unroll
    for (int ks = 0; ks < 4; ++ks) {
        const uint32_t uB = (uint32_t)(((ks * 2 + selB) ^ l7) * 16);
#pragma unroll
        for (int p = 0; p < 4; ++p)
            ldsm4(B[ks][p], aB0 + p * 2048 + uB);
    }

    // hoist bias fragments
    float2 bfr[8];
    {
        const float *bsp =
            reinterpret_cast<const float *>(smem + SM_BIAS) + wn * 64 + (lane & 3) * 2;
#pragma unroll
        for (int nf = 0; nf < 8; ++nf)
            bfr[nf] = *reinterpret_cast<const float2 *>(bsp + nf * 8);
    }

    // A-frag (trans) lane constants: chunk = (lane>>3)&1, j-in-16 = jjl
    const int jjl = (lane & 7) + ((lane >> 4) & 1) * 8;
    const uint32_t aA0 = wreg + (uint32_t)(((lane >> 3) & 1) * 1024 + jjl * 16);

    const float HI = 1.0f - 1e-5f;

    auto do_tile = [&](int t, int buf) {
        float acc[8][4];
#pragma unroll
        for (int nf = 0; nf < 8; ++nf)
#pragma unroll
            for (int c = 0; c < 4; ++c) acc[nf][c] = 0.f;

        const uint32_t aA = aA0 + (uint32_t)buf * SM_XBUF;
#pragma unroll
        for (int ks = 0; ks < 4; ++ks) {
            uint32_t Af[4];
            ldsm4t(Af, aA + (uint32_t)(ks * 256));   // 16 j rows x 16B contiguous
#pragma unroll
            for (int p = 0; p < 4; ++p) {
                mma16816(acc[2 * p],     Af, B[ks][p][0], B[ks][p][1]);
                mma16816(acc[2 * p + 1], Af, B[ks][p][2], B[ks][p][3]);
            }
        }

        const int m0 = (grp * 16 + t) * 64;
        float *opb = out + (size_t)(m0 + wm * 16 + (lane >> 2)) * 4096 + ki0 + wn * 64 +
                     (lane & 3) * 2;
#pragma unroll
        for (int h = 0; h < 2; ++h) {
            float v[8][2];
            float s = 0.f;
#pragma unroll
            for (int nf = 0; nf < 8; ++nf) {
                const float v0 = fminf(fmaxf(acc[nf][2 * h]     + bfr[nf].x, 1e-5f), HI);
                const float v1 = fminf(fmaxf(acc[nf][2 * h + 1] + bfr[nf].y, 1e-5f), HI);
                v[nf][0] = v0; v[nf][1] = v1;
                s += v0 + v1;
            }
            s += __shfl_xor_sync(0xffffffffu, s, 1);
            s += __shfl_xor_sync(0xffffffffu, s, 2);
            const float inv = __fdividef(1.0f, s);
            float *op = opb + h * (8 * 4096);
#pragma unroll
            for (int nf = 0; nf < 8; ++nf)
                *reinterpret_cast<float2 *>(op + nf * 8) =
                    make_float2(v[nf][0] * inv, v[nf][1] * inv);
        }
    };

#pragma unroll 1
    for (int t = 0; t < 16; ++t) {
        if (t + 3 < 16) stage_x(t + 3, (t + 3) & 3);
        // per-warp wait ladder: ensure tile t's group is complete
        if (t < 13)      cpa_wait<3>();
        else if (t == 13) cpa_wait<2>();
        else if (t == 14) cpa_wait<1>();
        else              cpa_wait<0>();
        do_tile(t, t & 3);
    }
}

// ---------------------------------------------------------------------------
extern "C" void kernel_launch(void *const *d_in, const int *in_sizes, int n_in,
                              void *d_out, int out_size) {
    const float *x  = (const float *)d_in[0];   // (4, 64, 16384) f32
    const float *cm = (const float *)d_in[1];   // (64, 64) f32
    const float *W  = (const float *)d_in[2];   // (64, 64, 128) f32
    float *out = (float *)d_out;                // (65536, 4096) f32

    (void)in_sizes; (void)n_in; (void)out_size;

    cudaFuncSetAttribute(mma_kernel, cudaFuncAttributeMaxDynamicSharedMemorySize, SM_TOTAL);
    prep_all<<<1280, 256>>>(x, W, cm);
    mma_kernel<<<dim3(32, 64), 256, SM_TOTAL>>>(out);
}

// round 13
// speedup vs baseline: 1.3549x; 1.3549x over previous
#include <cuda_runtime.h>
#include <cuda_fp16.h>
#include <cstdint>

#define NSEQ 16384

__device__ __half g_Wh[4096 * 64];        // [ki][j] fp16 W
__device__ float  g_bias[4096];           // [ki]
__device__ __half g_xh[4 * 64 * NSEQ];    // fp16 copy of x, same layout

// smem byte offsets
#define SM_W     0                    // [128 n][64 j] fp16 swizzled (16384)
#define SM_BIAS  16384                // 128 f32                      (512)
#define SM_X     16896                // 3 bufs x 8192: [64 j][64 m] fp16 swizzled
#define SM_XBUF  8192
#define SM_TOTAL (16896 + 3 * 8192)   // 41472

__device__ __forceinline__ uint32_t smem_u32(const void *p) {
    uint32_t a;
    asm("{ .reg .u64 t; cvta.to.shared.u64 t, %1; cvt.u32.u64 %0, t; }" : "=r"(a) : "l"(p));
    return a;
}
__device__ __forceinline__ uint32_t h2u(__half2 h) {
    return *reinterpret_cast<const uint32_t *>(&h);
}
__device__ __forceinline__ void ldsm4(uint32_t *r, uint32_t a) {
    asm volatile("ldmatrix.sync.aligned.m8n8.x4.shared.b16 {%0,%1,%2,%3}, [%4];"
                 : "=r"(r[0]), "=r"(r[1]), "=r"(r[2]), "=r"(r[3]) : "r"(a));
}
__device__ __forceinline__ void ldsm4t(uint32_t *r, uint32_t a) {
    asm volatile("ldmatrix.sync.aligned.m8n8.x4.trans.shared.b16 {%0,%1,%2,%3}, [%4];"
                 : "=r"(r[0]), "=r"(r[1]), "=r"(r[2]), "=r"(r[3]) : "r"(a));
}
__device__ __forceinline__ void mma16816(float *c, const uint32_t *a, uint32_t b0, uint32_t b1) {
    asm volatile("mma.sync.aligned.m16n8k16.row.col.f32.f16.f16.f32 "
                 "{%0,%1,%2,%3}, {%4,%5,%6,%7}, {%8,%9}, {%0,%1,%2,%3};"
                 : "+f"(c[0]), "+f"(c[1]), "+f"(c[2]), "+f"(c[3])
                 : "r"(a[0]), "r"(a[1]), "r"(a[2]), "r"(a[3]), "r"(b0), "r"(b1));
}
__device__ __forceinline__ void cpa16(uint32_t dst, const void *src) {
    asm volatile("cp.async.cg.shared.global [%0], [%1], 16;" :: "r"(dst), "l"(src));
}
__device__ __forceinline__ void cpa_commit() {
    asm volatile("cp.async.commit_group;" ::: "memory");
}
template <int N> __device__ __forceinline__ void cpa_wait() {
    asm volatile("cp.async.wait_group %0;" :: "n"(N) : "memory");
}

// ---------------------------------------------------------------------------
// Combined prep (one launch):
//   blocks [0, 1024):    x f32 -> fp16 g_xh (16 elems/thread)
//   blocks [1024, 1280): W -> fp16 g_Wh [ki][j] + bias[ki] = cm[k] . Wcm[k][i]
// ---------------------------------------------------------------------------
__global__ void prep_all(const float *__restrict__ x, const float *__restrict__ W,
                         const float *__restrict__ cm) {
    const int tid = threadIdx.x;
    if (blockIdx.x < 1024) {
        const int t = blockIdx.x * 256 + tid;
        const float4 *src = reinterpret_cast<const float4 *>(x) + (size_t)t * 4;
        uint4 *dst = reinterpret_cast<uint4 *>(g_xh) + (size_t)t * 2;
#pragma unroll
        for (int h = 0; h < 2; ++h) {
            float4 a = src[2 * h], b = src[2 * h + 1];
            uint32_t p0 = h2u(__float22half2_rn(make_float2(a.x, a.y)));
            uint32_t p1 = h2u(__float22half2_rn(make_float2(a.z, a.w)));
            uint32_t p2 = h2u(__float22half2_rn(make_float2(b.x, b.y)));
            uint32_t p3 = h2u(__float22half2_rn(make_float2(b.z, b.w)));
            dst[h] = make_uint4(p0, p1, p2, p3);
        }
    } else {
        const int pb = blockIdx.x - 1024;     // 0..255
#pragma unroll
        for (int t = 0; t < 4; ++t) {
            const int e = pb * 1024 + t * 256 + tid;   // (k, i, j) packed
            const int k = e >> 12, i = (e >> 6) & 63, j = e & 63;
            g_Wh[e] = __float2half_rn(W[(k * 64 + i) * 128 + j]);
        }
        if (tid < 16) {
            const int idx = pb * 16 + tid;    // ki
            const int k = idx >> 6, i = idx & 63;
            const float *cmk = cm + k * 64;
            const float *wc = W + (k * 64 + i) * 128 + 64;
            float s = 0.f;
#pragma unroll 8
            for (int j = 0; j < 64; ++j)
                s = fmaf(cmk[j], wc[j], s);
            g_bias[idx] = s;
        }
    }
}

// ---------------------------------------------------------------------------
// Main: 256 threads (8 warps = 4m x 2n), CTA tile 64m x 128ki, K=64.
// 16 m-tiles per CTA. X staged [64 j][64 m] fp16 via cp.async (3-stage),
// A frags via ldmatrix.trans. B reloaded from smem per ks (NOT hoisted) to
// cut registers -> 3 CTAs/SM (occ 36%). Plain coalesced float2 stores.
// ---------------------------------------------------------------------------
__global__ __launch_bounds__(256, 3)
void mma_kernel(float *__restrict__ out) {
    extern __shared__ char smem[];
    const uint32_t sb = smem_u32(smem);
    const int tid = threadIdx.x;
    const int lane = tid & 31, wid = tid >> 5;
    const int wm = wid & 3, wn = wid >> 2;
    const int ki0 = blockIdx.x * 128;
    const int grp = blockIdx.y;          // 0..63, 16 m-tiles of 64 each

    // ---- per-thread staging constants: 2 chunks (tid, tid+256) ----
    const int cj0 = tid >> 3, cp0 = tid & 7;
    const int cj1 = (tid + 256) >> 3, cp1 = tid & 7;
    const uint32_t d0 = sb + SM_X + (uint32_t)cj0 * 128 + (uint32_t)((cp0 ^ (cj0 & 7)) * 16);
    const uint32_t d1 = sb + SM_X + (uint32_t)cj1 * 128 + (uint32_t)((cp1 ^ (cj1 & 7)) * 16);

    auto stage_x = [&](int t, int buf) {
        const int m0 = (grp * 16 + t) * 64;
        const __half *xb = g_xh + ((size_t)(m0 >> 14) * 64) * NSEQ + (m0 & (NSEQ - 1));
        cpa16(d0 + (uint32_t)buf * SM_XBUF, xb + (size_t)cj0 * NSEQ + cp0 * 8);
        cpa16(d1 + (uint32_t)buf * SM_XBUF, xb + (size_t)cj1 * NSEQ + cp1 * 8);
        cpa_commit();
    };

    // prologue: start tiles 0,1
    stage_x(0, 0);
    stage_x(1, 1);

    // ---- stage W (swizzled, once) + bias ----
    {
#pragma unroll
        for (int q = 0; q < 4; ++q) {
            const int c = tid + q * 256;
            const int n = c >> 3, ch = c & 7;
            const uint4 w = *reinterpret_cast<const uint4 *>(g_Wh + (ki0 + n) * 64 + ch * 8);
            *reinterpret_cast<uint4 *>(smem + SM_W + n * 128 + ((ch ^ (n & 7)) * 16)) = w;
        }
        if (tid < 128) reinterpret_cast<float *>(smem + SM_BIAS)[tid] = g_bias[ki0 + tid];
    }

    cpa_wait<1>();
    __syncthreads();

    // lane constants
    const int l7 = lane & 7;
    const int rBl = (lane & 7) + ((lane >> 4) << 3);
    const uint32_t aB0 = sb + SM_W + (uint32_t)(wn * 64 + rBl) * 128;
    const int selB = (lane >> 3) & 1;
    const int jjl = (lane & 7) + ((lane >> 4) & 1) * 8;
    const int mcA = wm * 2 + ((lane >> 3) & 1);
    const uint32_t aA0 = sb + SM_X + (uint32_t)jjl * 128 + (uint32_t)((mcA ^ l7) * 16);
    const float *bsp =
        reinterpret_cast<const float *>(smem + SM_BIAS) + wn * 64 + (lane & 3) * 2;

    const float HI = 1.0f - 1e-5f;

    int buf = 0;
#pragma unroll 1
    for (int t = 0; t < 16; ++t) {
        if (t + 2 < 16) {
            int b2i = buf + 2; if (b2i >= 3) b2i -= 3;
            stage_x(t + 2, b2i);
        }

        float acc[8][4];
#pragma unroll
        for (int nf = 0; nf < 8; ++nf)
#pragma unroll
            for (int c = 0; c < 4; ++c) acc[nf][c] = 0.f;

        const uint32_t aA = aA0 + (uint32_t)buf * SM_XBUF;
#pragma unroll
        for (int ks = 0; ks < 4; ++ks) {
            uint32_t Af[4];
            ldsm4t(Af, aA + (uint32_t)ks * 2048);
            const uint32_t uB = (uint32_t)(((ks * 2 + selB) ^ l7) * 16);
#pragma unroll
            for (int p = 0; p < 4; ++p) {
                uint32_t Bf[4];
                ldsm4(Bf, aB0 + p * 2048 + uB);
                mma16816(acc[2 * p],     Af, Bf[0], Bf[1]);
                mma16816(acc[2 * p + 1], Af, Bf[2], Bf[3]);
            }
        }

        // ---- epilogue: bias + clip + L1-normalize + coalesced STG.64 ----
        const int m0 = (grp * 16 + t) * 64;
#pragma unroll
        for (int h = 0; h < 2; ++h) {
            float v[8][2];
            float s = 0.f;
#pragma unroll
            for (int nf = 0; nf < 8; ++nf) {
                const float2 bb = *reinterpret_cast<const float2 *>(bsp + nf * 8);
                const float v0 = fminf(fmaxf(acc[nf][2 * h]     + bb.x, 1e-5f), HI);
                const float v1 = fminf(fmaxf(acc[nf][2 * h + 1] + bb.y, 1e-5f), HI);
                v[nf][0] = v0; v[nf][1] = v1;
                s += v0 + v1;
            }
            s += __shfl_xor_sync(0xffffffffu, s, 1);
            s += __shfl_xor_sync(0xffffffffu, s, 2);
            const float inv = __fdividef(1.0f, s);
            const int row = wm * 16 + (lane >> 2) + h * 8;
            float *op = out + (size_t)(m0 + row) * 4096 + ki0 + wn * 64 + (lane & 3) * 2;
#pragma unroll
            for (int nf = 0; nf < 8; ++nf)
                *reinterpret_cast<float2 *>(op + nf * 8) =
                    make_float2(v[nf][0] * inv, v[nf][1] * inv);
        }

        if (t + 2 < 16) cpa_wait<1>();
        else            cpa_wait<0>();
        if (t < 15) __syncthreads();

        if (++buf == 3) buf = 0;
    }
}

// ---------------------------------------------------------------------------
extern "C" void kernel_launch(void *const *d_in, const int *in_sizes, int n_in,
                              void *d_out, int out_size) {
    const float *x  = (const float *)d_in[0];   // (4, 64, 16384) f32
    const float *cm = (const float *)d_in[1];   // (64, 64) f32
    const float *W  = (const float *)d_in[2];   // (64, 64, 128) f32
    float *out = (float *)d_out;                // (65536, 4096) f32

    (void)in_sizes; (void)n_in; (void)out_size;

    cudaFuncSetAttribute(mma_kernel, cudaFuncAttributeMaxDynamicSharedMemorySize, SM_TOTAL);
    prep_all<<<1280, 256>>>(x, W, cm);
    mma_kernel<<<dim3(32, 64), 256, SM_TOTAL>>>(out);
}

// round 14
// speedup vs baseline: 1.4047x; 1.0367x over previous
#include <cuda_runtime.h>
#include <cuda_fp16.h>
#include <cstdint>

#define NSEQ 16384

__device__ __half g_Wh[4096 * 64];        // [ki][j] fp16 W
__device__ float  g_bias[4096];           // [ki]
__device__ __half g_xh[4 * 64 * NSEQ];    // fp16 copy of x, same layout

// smem byte offsets
#define SM_W     0                    // [128 n][64 j] fp16 swizzled (16384)
#define SM_BIAS  16384                // 128 f32                      (512)
#define SM_X     16896                // 3 bufs x 8192: [64 j][64 m] fp16 swizzled
#define SM_XBUF  8192
#define SM_TOTAL (16896 + 3 * 8192)   // 41472

__device__ __forceinline__ uint32_t smem_u32(const void *p) {
    uint32_t a;
    asm("{ .reg .u64 t; cvta.to.shared.u64 t, %1; cvt.u32.u64 %0, t; }" : "=r"(a) : "l"(p));
    return a;
}
__device__ __forceinline__ uint32_t h2u(__half2 h) {
    return *reinterpret_cast<const uint32_t *>(&h);
}
__device__ __forceinline__ void ldsm4(uint32_t *r, uint32_t a) {
    asm volatile("ldmatrix.sync.aligned.m8n8.x4.shared.b16 {%0,%1,%2,%3}, [%4];"
                 : "=r"(r[0]), "=r"(r[1]), "=r"(r[2]), "=r"(r[3]) : "r"(a));
}
__device__ __forceinline__ void ldsm4t(uint32_t *r, uint32_t a) {
    asm volatile("ldmatrix.sync.aligned.m8n8.x4.trans.shared.b16 {%0,%1,%2,%3}, [%4];"
                 : "=r"(r[0]), "=r"(r[1]), "=r"(r[2]), "=r"(r[3]) : "r"(a));
}
__device__ __forceinline__ void mma16816(float *c, const uint32_t *a, uint32_t b0, uint32_t b1) {
    asm volatile("mma.sync.aligned.m16n8k16.row.col.f32.f16.f16.f32 "
                 "{%0,%1,%2,%3}, {%4,%5,%6,%7}, {%8,%9}, {%0,%1,%2,%3};"
                 : "+f"(c[0]), "+f"(c[1]), "+f"(c[2]), "+f"(c[3])
                 : "r"(a[0]), "r"(a[1]), "r"(a[2]), "r"(a[3]), "r"(b0), "r"(b1));
}
__device__ __forceinline__ void cpa16(uint32_t dst, const void *src) {
    asm volatile("cp.async.cg.shared.global [%0], [%1], 16;" :: "r"(dst), "l"(src));
}
__device__ __forceinline__ void cpa_commit() {
    asm volatile("cp.async.commit_group;" ::: "memory");
}
template <int N> __device__ __forceinline__ void cpa_wait() {
    asm volatile("cp.async.wait_group %0;" :: "n"(N) : "memory");
}

// ---------------------------------------------------------------------------
// Combined prep (one launch):
//   blocks [0, 1024):    x f32 -> fp16 g_xh (16 elems/thread)
//   blocks [1024, 1280): W -> fp16 g_Wh [ki][j] + bias[ki] = cm[k] . Wcm[k][i]
// ---------------------------------------------------------------------------
__global__ void prep_all(const float *__restrict__ x, const float *__restrict__ W,
                         const float *__restrict__ cm) {
    const int tid = threadIdx.x;
    if (blockIdx.x < 1024) {
        const int t = blockIdx.x * 256 + tid;
        const float4 *src = reinterpret_cast<const float4 *>(x) + (size_t)t * 4;
        uint4 *dst = reinterpret_cast<uint4 *>(g_xh) + (size_t)t * 2;
#pragma unroll
        for (int h = 0; h < 2; ++h) {
            float4 a = src[2 * h], b = src[2 * h + 1];
            uint32_t p0 = h2u(__float22half2_rn(make_float2(a.x, a.y)));
            uint32_t p1 = h2u(__float22half2_rn(make_float2(a.z, a.w)));
            uint32_t p2 = h2u(__float22half2_rn(make_float2(b.x, b.y)));
            uint32_t p3 = h2u(__float22half2_rn(make_float2(b.z, b.w)));
            dst[h] = make_uint4(p0, p1, p2, p3);
        }
    } else {
        const int pb = blockIdx.x - 1024;     // 0..255
#pragma unroll
        for (int t = 0; t < 4; ++t) {
            const int e = pb * 1024 + t * 256 + tid;   // (k, i, j) packed
            const int k = e >> 12, i = (e >> 6) & 63, j = e & 63;
            g_Wh[e] = __float2half_rn(W[(k * 64 + i) * 128 + j]);
        }
        if (tid < 16) {
            const int idx = pb * 16 + tid;    // ki
            const int k = idx >> 6, i = idx & 63;
            const float *cmk = cm + k * 64;
            const float *wc = W + (k * 64 + i) * 128 + 64;
            float s = 0.f;
#pragma unroll 8
            for (int j = 0; j < 64; ++j)
                s = fmaf(cmk[j], wc[j], s);
            g_bias[idx] = s;
        }
    }
}

// ---------------------------------------------------------------------------
// Main: 256 threads (8 warps = 4m x 2n), CTA tile 64m x 128ki, K=64.
// 16 m-tiles per CTA. X staged [64 j][64 m] fp16 via cp.async (3-stage),
// A frags via ldmatrix.trans. B (W) hoisted to regs once. 2 CTAs/SM.
// R14: all per-tile gmem addressing replaced by pointer increments
// (grp's 1024 m-rows never cross a batch boundary, so +64 / +64*4096 exact).
// ---------------------------------------------------------------------------
__global__ __launch_bounds__(256, 2)
void mma_kernel(float *__restrict__ out) {
    extern __shared__ char smem[];
    const uint32_t sb = smem_u32(smem);
    const int tid = threadIdx.x;
    const int lane = tid & 31, wid = tid >> 5;
    const int wm = wid & 3, wn = wid >> 2;
    const int ki0 = blockIdx.x * 128;
    const int grp = blockIdx.y;          // 0..63, 16 m-tiles of 64 each

    // ---- staging: per-thread 2 chunks; source pointers advance by 64/tile ----
    const int cj0 = tid >> 3, cp0 = tid & 7;
    const int cj1 = (tid + 256) >> 3, cp1 = tid & 7;
    const uint32_t d0 = sb + SM_X + (uint32_t)cj0 * 128 + (uint32_t)((cp0 ^ (cj0 & 7)) * 16);
    const uint32_t d1 = sb + SM_X + (uint32_t)cj1 * 128 + (uint32_t)((cp1 ^ (cj1 & 7)) * 16);

    const int mg0 = grp * 1024;          // first m-row of this grp (batch-aligned range)
    const __half *xg = g_xh + ((size_t)(mg0 >> 14) * 64) * NSEQ + (mg0 & (NSEQ - 1));
    const __half *s0 = xg + (size_t)cj0 * NSEQ + cp0 * 8;
    const __half *s1 = xg + (size_t)cj1 * NSEQ + cp1 * 8;

    auto stage_x = [&](int buf) {
        cpa16(d0 + (uint32_t)buf * SM_XBUF, s0);
        cpa16(d1 + (uint32_t)buf * SM_XBUF, s1);
        cpa_commit();
        s0 += 64; s1 += 64;
    };

    // prologue: start tiles 0,1
    stage_x(0);
    stage_x(1);

    // ---- stage W (swizzled, once) + bias ----
    {
#pragma unroll
        for (int q = 0; q < 4; ++q) {
            const int c = tid + q * 256;
            const int n = c >> 3, ch = c & 7;
            const uint4 w = *reinterpret_cast<const uint4 *>(g_Wh + (ki0 + n) * 64 + ch * 8);
            *reinterpret_cast<uint4 *>(smem + SM_W + n * 128 + ((ch ^ (n & 7)) * 16)) = w;
        }
        if (tid < 128) reinterpret_cast<float *>(smem + SM_BIAS)[tid] = g_bias[ki0 + tid];
    }

    cpa_wait<1>();
    __syncthreads();

    // ---- hoist B (W tile) fragments: constant for whole CTA ----
    const int l7 = lane & 7;
    const int rBl = (lane & 7) + ((lane >> 4) << 3);
    const uint32_t aB0 = sb + SM_W + (uint32_t)(wn * 64 + rBl) * 128;
    const int selB = (lane >> 3) & 1;
    uint32_t B[4][4][4];
#pragma unroll
    for (int ks = 0; ks < 4; ++ks) {
        const uint32_t uB = (uint32_t)(((ks * 2 + selB) ^ l7) * 16);
#pragma unroll
        for (int p = 0; p < 4; ++p)
            ldsm4(B[ks][p], aB0 + p * 2048 + uB);
    }

    // hoist bias fragments (loop-invariant across tiles)
    float2 bfr[8];
    {
        const float *bsp =
            reinterpret_cast<const float *>(smem + SM_BIAS) + wn * 64 + (lane & 3) * 2;
#pragma unroll
        for (int nf = 0; nf < 8; ++nf)
            bfr[nf] = *reinterpret_cast<const float2 *>(bsp + nf * 8);
    }

    // A-frag (trans) lane constants
    const int jjl = (lane & 7) + ((lane >> 4) & 1) * 8;
    const int mcA = wm * 2 + ((lane >> 3) & 1);
    const uint32_t aA0 = sb + SM_X + (uint32_t)jjl * 128 + (uint32_t)((mcA ^ l7) * 16);

    // output pointer: advances by 64 rows * 4096 floats per tile
    float *opb = out + (size_t)(mg0 + wm * 16 + (lane >> 2)) * 4096 + ki0 + wn * 64 +
                 (lane & 3) * 2;

    const float HI = 1.0f - 1e-5f;

    int buf = 0;
#pragma unroll 1
    for (int t = 0; t < 16; ++t) {
        if (t + 2 < 16) {
            int b2i = buf + 2; if (b2i >= 3) b2i -= 3;
            stage_x(b2i);
        }

        float acc[8][4];
#pragma unroll
        for (int nf = 0; nf < 8; ++nf)
#pragma unroll
            for (int c = 0; c < 4; ++c) acc[nf][c] = 0.f;

        const uint32_t aA = aA0 + (uint32_t)buf * SM_XBUF;
#pragma unroll
        for (int ks = 0; ks < 4; ++ks) {
            uint32_t Af[4];
            ldsm4t(Af, aA + (uint32_t)ks * 2048);
#pragma unroll
            for (int p = 0; p < 4; ++p) {
                mma16816(acc[2 * p],     Af, B[ks][p][0], B[ks][p][1]);
                mma16816(acc[2 * p + 1], Af, B[ks][p][2], B[ks][p][3]);
            }
        }

        // ---- epilogue: bias + clip + L1-normalize + coalesced STG.64 ----
#pragma unroll
        for (int h = 0; h < 2; ++h) {
            float v[8][2];
            float s = 0.f;
#pragma unroll
            for (int nf = 0; nf < 8; ++nf) {
                const float v0 = fminf(fmaxf(acc[nf][2 * h]     + bfr[nf].x, 1e-5f), HI);
                const float v1 = fminf(fmaxf(acc[nf][2 * h + 1] + bfr[nf].y, 1e-5f), HI);
                v[nf][0] = v0; v[nf][1] = v1;
                s += v0 + v1;
            }
            s += __shfl_xor_sync(0xffffffffu, s, 1);
            s += __shfl_xor_sync(0xffffffffu, s, 2);
            const float inv = __fdividef(1.0f, s);
            float *op = opb + h * (8 * 4096);
#pragma unroll
            for (int nf = 0; nf < 8; ++nf)
                *reinterpret_cast<float2 *>(op + nf * 8) =
                    make_float2(v[nf][0] * inv, v[nf][1] * inv);
        }
        opb += 64 * 4096;

        if (t + 2 < 16) cpa_wait<1>();
        else            cpa_wait<0>();
        if (t < 15) __syncthreads();

        if (++buf == 3) buf = 0;
    }
}

// ---------------------------------------------------------------------------
extern "C" void kernel_launch(void *const *d_in, const int *in_sizes, int n_in,
                              void *d_out, int out_size) {
    const float *x  = (const float *)d_in[0];   // (4, 64, 16384) f32
    const float *cm = (const float *)d_in[1];   // (64, 64) f32
    const float *W  = (const float *)d_in[2];   // (64, 64, 128) f32
    float *out = (float *)d_out;                // (65536, 4096) f32

    (void)in_sizes; (void)n_in; (void)out_size;

    cudaFuncSetAttribute(mma_kernel, cudaFuncAttributeMaxDynamicSharedMemorySize, SM_TOTAL);
    prep_all<<<1280, 256>>>(x, W, cm);
    mma_kernel<<<dim3(32, 64), 256, SM_TOTAL>>>(out);
}

// round 15
// speedup vs baseline: 1.6139x; 1.1489x over previous
#include <cuda_runtime.h>
#include <cuda_fp16.h>
#include <cstdint>

#define NSEQ 16384

__device__ __half g_Wh[4096 * 64];        // [ki][j] fp16 W
__device__ float  g_bias[4096];           // [ki]
__device__ __half g_xh[4 * 64 * NSEQ];    // fp16 copy of x, same layout

// smem byte offsets
#define SM_W     0                    // [128 n][64 j] fp16 swizzled (16384)
#define SM_BIAS  16384                // 128 f32                      (512)
#define SM_X     16896                // 3 bufs x 8192: [64 j][64 m] fp16 swizzled
#define SM_XBUF  8192
#define SM_TOTAL (16896 + 3 * 8192)   // 41472

__device__ __forceinline__ uint32_t smem_u32(const void *p) {
    uint32_t a;
    asm("{ .reg .u64 t; cvta.to.shared.u64 t, %1; cvt.u32.u64 %0, t; }" : "=r"(a) : "l"(p));
    return a;
}
__device__ __forceinline__ uint32_t h2u(__half2 h) {
    return *reinterpret_cast<const uint32_t *>(&h);
}
__device__ __forceinline__ void ldsm4(uint32_t *r, uint32_t a) {
    asm volatile("ldmatrix.sync.aligned.m8n8.x4.shared.b16 {%0,%1,%2,%3}, [%4];"
                 : "=r"(r[0]), "=r"(r[1]), "=r"(r[2]), "=r"(r[3]) : "r"(a));
}
__device__ __forceinline__ void ldsm4t(uint32_t *r, uint32_t a) {
    asm volatile("ldmatrix.sync.aligned.m8n8.x4.trans.shared.b16 {%0,%1,%2,%3}, [%4];"
                 : "=r"(r[0]), "=r"(r[1]), "=r"(r[2]), "=r"(r[3]) : "r"(a));
}
__device__ __forceinline__ void mma16816(float *c, const uint32_t *a, uint32_t b0, uint32_t b1) {
    asm volatile("mma.sync.aligned.m16n8k16.row.col.f32.f16.f16.f32 "
                 "{%0,%1,%2,%3}, {%4,%5,%6,%7}, {%8,%9}, {%0,%1,%2,%3};"
                 : "+f"(c[0]), "+f"(c[1]), "+f"(c[2]), "+f"(c[3])
                 : "r"(a[0]), "r"(a[1]), "r"(a[2]), "r"(a[3]), "r"(b0), "r"(b1));
}
__device__ __forceinline__ void cpa16(uint32_t dst, const void *src) {
    asm volatile("cp.async.cg.shared.global [%0], [%1], 16;" :: "r"(dst), "l"(src));
}
__device__ __forceinline__ void cpa_commit() {
    asm volatile("cp.async.commit_group;" ::: "memory");
}
template <int N> __device__ __forceinline__ void cpa_wait() {
    asm volatile("cp.async.wait_group %0;" :: "n"(N) : "memory");
}

// ---------------------------------------------------------------------------
// Combined prep (one launch):
//   blocks [0, 1024):    x f32 -> fp16 g_xh (16 elems/thread)
//   blocks [1024, 1280): W -> fp16 g_Wh [ki][j] + bias[ki] = cm[k] . Wcm[k][i]
// ---------------------------------------------------------------------------
__global__ void prep_all(const float *__restrict__ x, const float *__restrict__ W,
                         const float *__restrict__ cm) {
    const int tid = threadIdx.x;
    if (blockIdx.x < 1024) {
        const int t = blockIdx.x * 256 + tid;
        const float4 *src = reinterpret_cast<const float4 *>(x) + (size_t)t * 4;
        uint4 *dst = reinterpret_cast<uint4 *>(g_xh) + (size_t)t * 2;
#pragma unroll
        for (int h = 0; h < 2; ++h) {
            float4 a = src[2 * h], b = src[2 * h + 1];
            uint32_t p0 = h2u(__float22half2_rn(make_float2(a.x, a.y)));
            uint32_t p1 = h2u(__float22half2_rn(make_float2(a.z, a.w)));
            uint32_t p2 = h2u(__float22half2_rn(make_float2(b.x, b.y)));
            uint32_t p3 = h2u(__float22half2_rn(make_float2(b.z, b.w)));
            dst[h] = make_uint4(p0, p1, p2, p3);
        }
    } else {
        const int pb = blockIdx.x - 1024;     // 0..255
#pragma unroll
        for (int t = 0; t < 4; ++t) {
            const int e = pb * 1024 + t * 256 + tid;   // (k, i, j) packed
            const int k = e >> 12, i = (e >> 6) & 63, j = e & 63;
            g_Wh[e] = __float2half_rn(W[(k * 64 + i) * 128 + j]);
        }
        if (tid < 16) {
            const int idx = pb * 16 + tid;    // ki
            const int k = idx >> 6, i = idx & 63;
            const float *cmk = cm + k * 64;
            const float *wc = W + (k * 64 + i) * 128 + 64;
            float s = 0.f;
#pragma unroll 8
            for (int j = 0; j < 64; ++j)
                s = fmaf(cmk[j], wc[j], s);
            g_bias[idx] = s;
        }
    }
}

// ---------------------------------------------------------------------------
// Main (exact R7 configuration -- empirically fastest): 256 threads
// (8 warps = 4m x 2n), CTA tile 64m x 128ki, K=64, 16 m-tiles per CTA.
// X staged via cp.async (3-stage), A frags via ldmatrix.trans, B hoisted to
// regs once, bias read from smem in the epilogue, fresh per-tile addressing,
// plain coalesced float2 stores. 2 CTAs/SM.
// ---------------------------------------------------------------------------
__global__ __launch_bounds__(256, 2)
void mma_kernel(float *__restrict__ out) {
    extern __shared__ char smem[];
    const uint32_t sb = smem_u32(smem);
    const int tid = threadIdx.x;
    const int lane = tid & 31, wid = tid >> 5;
    const int wm = wid & 3, wn = wid >> 2;
    const int ki0 = blockIdx.x * 128;
    const int grp = blockIdx.y;          // 0..63, 16 m-tiles of 64 each

    // ---- per-thread staging constants: 2 chunks (tid, tid+256) ----
    const int cj0 = tid >> 3, cp0 = tid & 7;
    const int cj1 = (tid + 256) >> 3, cp1 = tid & 7;
    const uint32_t d0 = sb + SM_X + (uint32_t)cj0 * 128 + (uint32_t)((cp0 ^ (cj0 & 7)) * 16);
    const uint32_t d1 = sb + SM_X + (uint32_t)cj1 * 128 + (uint32_t)((cp1 ^ (cj1 & 7)) * 16);

    auto stage_x = [&](int t, int buf) {
        const int m0 = (grp * 16 + t) * 64;
        const __half *xb = g_xh + ((size_t)(m0 >> 14) * 64) * NSEQ + (m0 & (NSEQ - 1));
        cpa16(d0 + (uint32_t)buf * SM_XBUF, xb + (size_t)cj0 * NSEQ + cp0 * 8);
        cpa16(d1 + (uint32_t)buf * SM_XBUF, xb + (size_t)cj1 * NSEQ + cp1 * 8);
        cpa_commit();
    };

    // prologue: start tiles 0,1
    stage_x(0, 0);
    stage_x(1, 1);

    // ---- stage W (swizzled, once) + bias ----
    {
#pragma unroll
        for (int q = 0; q < 4; ++q) {
            const int c = tid + q * 256;
            const int n = c >> 3, ch = c & 7;
            const uint4 w = *reinterpret_cast<const uint4 *>(g_Wh + (ki0 + n) * 64 + ch * 8);
            *reinterpret_cast<uint4 *>(smem + SM_W + n * 128 + ((ch ^ (n & 7)) * 16)) = w;
        }
        if (tid < 128) reinterpret_cast<float *>(smem + SM_BIAS)[tid] = g_bias[ki0 + tid];
    }

    cpa_wait<1>();        // tile 0 resident
    __syncthreads();

    // ---- hoist B (W tile) fragments: constant for whole CTA ----
    const int l7 = lane & 7;
    const int rBl = (lane & 7) + ((lane >> 4) << 3);
    const uint32_t aB0 = sb + SM_W + (uint32_t)(wn * 64 + rBl) * 128;
    const int selB = (lane >> 3) & 1;
    uint32_t B[4][4][4];
#pragma unroll
    for (int ks = 0; ks < 4; ++ks) {
        const uint32_t uB = (uint32_t)(((ks * 2 + selB) ^ l7) * 16);
#pragma unroll
        for (int p = 0; p < 4; ++p)
            ldsm4(B[ks][p], aB0 + p * 2048 + uB);
    }

    // A-frag (trans) lane constants
    const int jjl = (lane & 7) + ((lane >> 4) & 1) * 8;
    const int mcA = wm * 2 + ((lane >> 3) & 1);
    const uint32_t aA0 = sb + SM_X + (uint32_t)jjl * 128 + (uint32_t)((mcA ^ l7) * 16);

    const float *bsp = reinterpret_cast<const float *>(smem + SM_BIAS) + wn * 64 + (lane & 3) * 2;
    const float HI = 1.0f - 1e-5f;

    int buf = 0;
#pragma unroll 1
    for (int t = 0; t < 16; ++t) {
        if (t + 2 < 16) {
            int b2i = buf + 2; if (b2i >= 3) b2i -= 3;
            stage_x(t + 2, b2i);
        }

        float acc[8][4];
#pragma unroll
        for (int nf = 0; nf < 8; ++nf)
#pragma unroll
            for (int c = 0; c < 4; ++c) acc[nf][c] = 0.f;

        const uint32_t aA = aA0 + (uint32_t)buf * SM_XBUF;
#pragma unroll
        for (int ks = 0; ks < 4; ++ks) {
            uint32_t Af[4];
            ldsm4t(Af, aA + (uint32_t)ks * 2048);
#pragma unroll
            for (int p = 0; p < 4; ++p) {
                mma16816(acc[2 * p],     Af, B[ks][p][0], B[ks][p][1]);
                mma16816(acc[2 * p + 1], Af, B[ks][p][2], B[ks][p][3]);
            }
        }

        // ---- epilogue: bias + clip + L1-normalize + direct store ----
        const int m0 = (grp * 16 + t) * 64;
#pragma unroll
        for (int h = 0; h < 2; ++h) {
            float v[8][2];
            float s = 0.f;
#pragma unroll
            for (int nf = 0; nf < 8; ++nf) {
                const float2 bb = *reinterpret_cast<const float2 *>(bsp + nf * 8);
                const float v0 = fminf(fmaxf(acc[nf][2 * h]     + bb.x, 1e-5f), HI);
                const float v1 = fminf(fmaxf(acc[nf][2 * h + 1] + bb.y, 1e-5f), HI);
                v[nf][0] = v0; v[nf][1] = v1;
                s += v0 + v1;
            }
            s += __shfl_xor_sync(0xffffffffu, s, 1);
            s += __shfl_xor_sync(0xffffffffu, s, 2);
            const float inv = __fdividef(1.0f, s);
            const int row = wm * 16 + (lane >> 2) + h * 8;
            float *op = out + (size_t)(m0 + row) * 4096 + ki0 + wn * 64 + (lane & 3) * 2;
#pragma unroll
            for (int nf = 0; nf < 8; ++nf)
                *reinterpret_cast<float2 *>(op + nf * 8) =
                    make_float2(v[nf][0] * inv, v[nf][1] * inv);
        }

        if (t + 2 < 16) cpa_wait<1>();   // tile t+1 resident (t+2 may be in flight)
        else            cpa_wait<0>();
        if (t < 15) __syncthreads();

        if (++buf == 3) buf = 0;
    }
}

// ---------------------------------------------------------------------------
extern "C" void kernel_launch(void *const *d_in, const int *in_sizes, int n_in,
                              void *d_out, int out_size) {
    const float *x  = (const float *)d_in[0];   // (4, 64, 16384) f32
    const float *cm = (const float *)d_in[1];   // (64, 64) f32
    const float *W  = (const float *)d_in[2];   // (64, 64, 128) f32
    float *out = (float *)d_out;                // (65536, 4096) f32

    (void)in_sizes; (void)n_in; (void)out_size;

    cudaFuncSetAttribute(mma_kernel, cudaFuncAttributeMaxDynamicSharedMemorySize, SM_TOTAL);
    prep_all<<<1280, 256>>>(x, W, cm);
    mma_kernel<<<dim3(32, 64), 256, SM_TOTAL>>>(out);
}